// round 15
// baseline (speedup 1.0000x reference)
#include <cuda_runtime.h>
#include <cuda_fp16.h>
#include <cstdint>

// Problem constants
#define Bsz 1024
#define Nn  50
#define Ll  50
#define Dd  128
#define Mrows (Bsz * Nn)   // 51200

// ---------------------------------------------------------------------------
// Device scratch. Pure fp16 operands.
// ---------------------------------------------------------------------------
__device__ __align__(256) __half  g_hiddenH[Mrows * 128];
__device__ __align__(256) __half  g_bigH[Mrows * 640];      // [h_in|h_out|gh(384)]
__device__ __align__(256) __half  g_inpH[Mrows * 256];      // [in|out]
__device__ __align__(256) __half  g_giH[Mrows * 384];
__device__ __align__(256) __half  g_seqH[Mrows * 128];
__device__ __align__(256) __half  g_alpH[Mrows * 128];
__device__ __align__(256) float   g_ht[Bsz * Dd];
__device__ __align__(256) float   g_q1[Bsz * Dd];
__device__ __align__(256) float   g_aht[Bsz * 256];
__device__ __align__(256) __half  g_WcatH[640 * 128];
__device__ __align__(256) __half  g_wihH[384 * 256];
__device__ __align__(256) __half  g_w2H[128 * 128];
__device__ __align__(256) __half  g_w3H[128 * 128];
__device__ __align__(256) float   g_bcat[640];

__device__ __forceinline__ float sigmoidf_(float x) {
    return 1.0f / (1.0f + __expf(-x));
}
__device__ __forceinline__ unsigned pkh2(float a, float b) {
    __half ha = __float2half_rn(a), hb = __float2half_rn(b);
    unsigned short ua = *reinterpret_cast<unsigned short*>(&ha);
    unsigned short ub = *reinterpret_cast<unsigned short*>(&hb);
    return (unsigned)ua | ((unsigned)ub << 16);
}
__device__ __forceinline__ uint32_t smem_u32(const void* p) {
    uint32_t a;
    asm("{ .reg .u64 t; cvta.to.shared.u64 t, %1; cvt.u32.u64 %0, t; }" : "=r"(a) : "l"(p));
    return a;
}

// ---------------------------------------------------------------------------
// Portable tensor-core primitives (compute_103-safe PTX)
// ---------------------------------------------------------------------------
#define CP_ASYNC16(sm, gm) \
    asm volatile("cp.async.cg.shared.global [%0], [%1], 16;" :: "r"(sm), "l"(gm))
#define CP_COMMIT() asm volatile("cp.async.commit_group;" ::: "memory")
#define CP_WAIT1()  asm volatile("cp.async.wait_group 1;" ::: "memory")

#define LDSM_X4(r0, r1, r2, r3, addr) \
    asm volatile("ldmatrix.sync.aligned.m8n8.x4.shared.b16 {%0,%1,%2,%3}, [%4];" \
                 : "=r"(r0), "=r"(r1), "=r"(r2), "=r"(r3) : "r"(addr))
#define LDSM_X2(r0, r1, addr) \
    asm volatile("ldmatrix.sync.aligned.m8n8.x2.shared.b16 {%0,%1}, [%2];" \
                 : "=r"(r0), "=r"(r1) : "r"(addr))
#define LDSM_X2_TRANS(r0, r1, addr) \
    asm volatile("ldmatrix.sync.aligned.m8n8.x2.trans.shared.b16 {%0,%1}, [%2];" \
                 : "=r"(r0), "=r"(r1) : "r"(addr))

#define MMA_F16(c0, c1, c2, c3, a0, a1, a2, a3, b0, b1) \
    asm volatile("mma.sync.aligned.m16n8k16.row.col.f32.f16.f16.f32 " \
                 "{%0,%1,%2,%3}, {%4,%5,%6,%7}, {%8,%9}, {%0,%1,%2,%3};" \
                 : "+f"(c0), "+f"(c1), "+f"(c2), "+f"(c3) \
                 : "r"(a0), "r"(a1), "r"(a2), "r"(a3), "r"(b0), "r"(b1))

// ---------------------------------------------------------------------------
// Merged prep: blocks [0,6400) gather hiddenH; blocks [6400,7232) convert W.
// ---------------------------------------------------------------------------
__global__ void prep_kernel(const int* __restrict__ items,
                            const float* __restrict__ emb,
                            const float* __restrict__ w_in,
                            const float* __restrict__ w_out,
                            const float* __restrict__ w_hh,
                            const float* __restrict__ bi_in,
                            const float* __restrict__ bi_out,
                            const float* __restrict__ b_hh,
                            const float* __restrict__ w_ih,
                            const float* __restrict__ w2,
                            const float* __restrict__ w3) {
    if (blockIdx.x < 6400) {
        int idx = blockIdx.x * 256 + threadIdx.x;   // Mrows * 32
        int row = idx >> 5, c4 = idx & 31;
        int it = items[row];
        float4 v = reinterpret_cast<const float4*>(emb)[(size_t)it * 32 + c4];
        uint2 hv;
        hv.x = pkh2(v.x, v.y);
        hv.y = pkh2(v.z, v.w);
        *reinterpret_cast<uint2*>(g_hiddenH + (size_t)row * 128 + c4 * 4) = hv;
        return;
    }
    int i = (blockIdx.x - 6400) * 256 + threadIdx.x;
    const int S0 = 640 * 128, S1 = 384 * 256, S2 = 128 * 128;
    if (i < S0) {
        int r = i >> 7, c = i & 127;
        float v = (r < 128) ? w_in[r * 128 + c]
                : (r < 256) ? w_out[(r - 128) * 128 + c]
                            : w_hh[(r - 256) * 128 + c];
        g_WcatH[i] = __float2half_rn(v);
    } else if (i < S0 + S1) {
        g_wihH[i - S0] = __float2half_rn(w_ih[i - S0]);
    } else if (i < S0 + S1 + S2) {
        g_w2H[i - S0 - S1] = __float2half_rn(w2[i - S0 - S1]);
    } else if (i < S0 + S1 + 2 * S2) {
        g_w3H[i - S0 - S1 - S2] = __float2half_rn(w3[i - S0 - S1 - S2]);
    }
    if (i < 640)
        g_bcat[i] = (i < 128) ? bi_in[i] : (i < 256 ? bi_out[i - 128] : b_hh[i - 256]);
}

// ---------------------------------------------------------------------------
// HMMA fp16 GEMM, 64x128 C-tile, 8 warps (2x4), warp tile 32x32.
// 3-stage chunk pipeline; 3 CTAs/SM (launch_bounds 256,3).
// smem: A stages [0,3*5120), W stages [15360, 15360+3*10240) = 46080 total.
// mode 2: fp16 out Ch at stride ldc
// mode 3: fused attention double-GEMM (gridDim.x==1, Kbase==128):
//   sigmoid vals -> 4 chunks at [0,20480) stride 5120;
//   W3 -> 4 chunks at [20480, 61440) stride 10240. dyn smem 61440.
// ---------------------------------------------------------------------------
#define ASTG 5120                      // A stage bytes: 64 rows * 40 halves * 2
#define WSTG 10240                     // W stage bytes: 128 rows * 40 halves * 2
#define AWOFF 15360                    // W region offset (3*ASTG)
#define HGEMM_SMEM2 46080              // modes 2 (3*ASTG + 3*WSTG)
#define HGEMM_SMEM3 61440              // mode 3 (4*ASTG sigmoid + 4*WSTG W3)

__global__ __launch_bounds__(256, 3)
void hgemm_kernel(const __half* __restrict__ A2,
                  const __half* __restrict__ W2,
                  const float* __restrict__ bias,
                  __half* __restrict__ Ch,
                  const __half* __restrict__ W3, const float* __restrict__ bias3,
                  __half* __restrict__ CalpH,
                  int Kbase, int ldc, const float* __restrict__ aux, int mode) {
    extern __shared__ __align__(16) __half smem[];

    const int tid = threadIdx.x;
    const int lane = tid & 31;
    const int wid = tid >> 5;
    const int warp_m = wid >> 2;        // 0..1 (32 rows each)
    const int warp_n = wid & 3;         // 0..3 (32 cols each)
    const int bm = blockIdx.y * 64, bn = blockIdx.x * 128;
    const int nch = Kbase >> 5;

    const uint32_t sbase = smem_u32(smem);
    // A loads: 256 uint4/chunk; thread -> row=tid>>2 (0..63), seg=tid&3
    const int a_row = tid >> 2, a_seg = tid & 3;
    const uint32_t a_st = (uint32_t)(a_row * 40 + a_seg * 8) * 2;
    const __half* Abase = A2 + (size_t)(bm + a_row) * Kbase + a_seg * 8;
    // W loads: 512 uint4/chunk; thread -> row=tid>>1 (0..127), 2 segs
    const int w_row = tid >> 1, w_seg = (tid & 1) << 1;
    const uint32_t w_st = (uint32_t)(w_row * 40 + w_seg * 8) * 2;
    const __half* Wbase = W2 + (size_t)(bn + w_row) * Kbase + w_seg * 8;

#define ISSUE(cc) do {                                                         \
        uint32_t st = (uint32_t)((cc) % 3);                                    \
        uint32_t da = sbase + st * ASTG + a_st;                                \
        uint32_t db = sbase + AWOFF + st * WSTG + w_st;                        \
        const __half* ga = Abase + (cc) * 32;                                  \
        const __half* gb = Wbase + (cc) * 32;                                  \
        CP_ASYNC16(da,      ga);                                               \
        CP_ASYNC16(db,      gb);                                               \
        CP_ASYNC16(db + 16, gb + 8);                                           \
        CP_COMMIT();                                                           \
    } while (0)

    float acc[2][4][4];
#pragma unroll
    for (int i = 0; i < 2; ++i)
#pragma unroll
        for (int j = 0; j < 4; ++j)
#pragma unroll
            for (int r = 0; r < 4; ++r) acc[i][j][r] = 0.0f;

    const uint32_t a_off = (uint32_t)((warp_m * 32 + (lane & 15)) * 40 + (lane >> 4) * 8);
    const uint32_t b_off = (uint32_t)((warp_n * 32 + (lane & 7)) * 40 + ((lane >> 3) & 1) * 8);

    ISSUE(0);
    ISSUE(1);

    for (int c = 0; c < nch; ++c) {
        CP_WAIT1();
        __syncthreads();
        if (c + 2 < nch) ISSUE(c + 2);
        else CP_COMMIT();

        const uint32_t st = (uint32_t)(c % 3);
        const uint32_t baseA = sbase + st * ASTG;
        const uint32_t baseB = sbase + AWOFF + st * WSTG;
#pragma unroll
        for (int ks = 0; ks < 2; ++ks) {
            uint32_t a[2][4], b[4][2];
#pragma unroll
            for (int mt = 0; mt < 2; ++mt)
                LDSM_X4(a[mt][0], a[mt][1], a[mt][2], a[mt][3],
                        baseA + (a_off + mt * 16 * 40 + ks * 16) * 2);
#pragma unroll
            for (int nt = 0; nt < 4; ++nt)
                LDSM_X2(b[nt][0], b[nt][1],
                        baseB + (b_off + nt * 8 * 40 + ks * 16) * 2);
#pragma unroll
            for (int mt = 0; mt < 2; ++mt)
#pragma unroll
                for (int nt = 0; nt < 4; ++nt)
                    MMA_F16(acc[mt][nt][0], acc[mt][nt][1], acc[mt][nt][2], acc[mt][nt][3],
                            a[mt][0], a[mt][1], a[mt][2], a[mt][3],
                            b[nt][0], b[nt][1]);
        }
    }
#undef ISSUE

    const int er = warp_m * 32 + (lane >> 2);
    const int ec = warp_n * 32 + (lane & 3) * 2;

    if (mode == 2) {
#pragma unroll
        for (int mt = 0; mt < 2; ++mt)
#pragma unroll
            for (int nt = 0; nt < 4; ++nt) {
                int row = bm + er + mt * 16;
                int col = bn + ec + nt * 8;
                float b0 = bias[col], b1 = bias[col + 1];
                unsigned h0 = pkh2(acc[mt][nt][0] + b0, acc[mt][nt][1] + b1);
                unsigned h1 = pkh2(acc[mt][nt][2] + b0, acc[mt][nt][3] + b1);
                *reinterpret_cast<unsigned*>(Ch + (size_t)row * ldc + col) = h0;
                *reinterpret_cast<unsigned*>(Ch + (size_t)(row + 8) * ldc + col) = h1;
            }
    } else {
        // ---- mode 3: sigmoid -> smem chunks [0,20480) -> GEMM2 with W3 ----
        __syncthreads();   // operand smem dead
        char* smc = reinterpret_cast<char*>(smem);
        const uint32_t W3OFF = 20480;
#pragma unroll
        for (int mt = 0; mt < 2; ++mt)
#pragma unroll
            for (int nt = 0; nt < 4; ++nt) {
                int col = ec + nt * 8;       // bn == 0
                float b0 = bias[col], b1 = bias[col + 1];
                int chunk = col >> 5, kk = col & 31;
#pragma unroll
                for (int h = 0; h < 2; ++h) {
                    int rl = er + mt * 16 + h * 8;     // 0..63
                    const float* ap = aux + (size_t)((bm + rl) / 50) * 128;
                    float v0 = sigmoidf_(acc[mt][nt][h * 2 + 0] + b0 + ap[col]);
                    float v1 = sigmoidf_(acc[mt][nt][h * 2 + 1] + b1 + ap[col + 1]);
                    *reinterpret_cast<unsigned*>(
                        smc + chunk * ASTG + rl * 80 + kk * 2) = pkh2(v0, v1);
                }
            }
        {   // stage W3 (128x128) into 4 chunks at W3OFF
            int row = tid >> 1, seg = (tid & 1) << 1;
            const uint4* w3v = reinterpret_cast<const uint4*>(W3);
#pragma unroll
            for (int cch = 0; cch < 4; ++cch) {
                uint4 v0 = w3v[row * 16 + cch * 4 + seg];
                uint4 v1 = w3v[row * 16 + cch * 4 + seg + 1];
                char* dst = smc + W3OFF + cch * WSTG + row * 80 + seg * 16;
                *reinterpret_cast<uint4*>(dst)      = v0;
                *reinterpret_cast<uint4*>(dst + 16) = v1;
            }
        }
        __syncthreads();
        float acc2[2][4][4];
#pragma unroll
        for (int i = 0; i < 2; ++i)
#pragma unroll
            for (int j = 0; j < 4; ++j)
#pragma unroll
                for (int r = 0; r < 4; ++r) acc2[i][j][r] = 0.0f;
#pragma unroll
        for (int c2 = 0; c2 < 4; ++c2) {
            const uint32_t baseA = sbase + c2 * ASTG;
            const uint32_t baseB = sbase + W3OFF + c2 * WSTG;
#pragma unroll
            for (int ks = 0; ks < 2; ++ks) {
                uint32_t a[2][4], b[4][2];
#pragma unroll
                for (int mt = 0; mt < 2; ++mt)
                    LDSM_X4(a[mt][0], a[mt][1], a[mt][2], a[mt][3],
                            baseA + (a_off + mt * 16 * 40 + ks * 16) * 2);
#pragma unroll
                for (int nt = 0; nt < 4; ++nt)
                    LDSM_X2(b[nt][0], b[nt][1],
                            baseB + (b_off + nt * 8 * 40 + ks * 16) * 2);
#pragma unroll
                for (int mt = 0; mt < 2; ++mt)
#pragma unroll
                    for (int nt = 0; nt < 4; ++nt)
                        MMA_F16(acc2[mt][nt][0], acc2[mt][nt][1], acc2[mt][nt][2], acc2[mt][nt][3],
                                a[mt][0], a[mt][1], a[mt][2], a[mt][3],
                                b[nt][0], b[nt][1]);
            }
        }
#pragma unroll
        for (int mt = 0; mt < 2; ++mt)
#pragma unroll
            for (int nt = 0; nt < 4; ++nt) {
                int row = bm + er + mt * 16;
                int col = ec + nt * 8;
                float b0 = bias3[col], b1 = bias3[col + 1];
                unsigned h0 = pkh2(acc2[mt][nt][0] + b0, acc2[mt][nt][1] + b1);
                unsigned h1 = pkh2(acc2[mt][nt][2] + b0, acc2[mt][nt][3] + b1);
                *reinterpret_cast<unsigned*>(CalpH + (size_t)row * 128 + col) = h0;
                *reinterpret_cast<unsigned*>(CalpH + (size_t)(row + 8) * 128 + col) = h1;
            }
    }
}

// ---------------------------------------------------------------------------
// HMMA graph matmul with row-major h + ldmatrix.trans.
// sA[i][j] 64x64 (zero-padded); sH[j][d] 64x128 (zero-padded rows >=50).
// ---------------------------------------------------------------------------
#define GASTR 72
#define GHSTR 136
__global__ __launch_bounds__(256)
void graph_mm_kernel(const float* __restrict__ Aadj,
                     const float* __restrict__ b_iah,
                     const float* __restrict__ b_oah) {
    __shared__ __align__(16) __half sA[64 * GASTR];
    __shared__ __align__(16) __half sH[64 * GHSTR];
    const int b = blockIdx.x, tid = threadIdx.x;
    const int lane = tid & 31, wid = tid >> 5;
    const int warp_m = wid >> 2;
    const int warp_n = wid & 3;

    {
        uint4 z = {0, 0, 0, 0};
        uint4* pa = reinterpret_cast<uint4*>(sA);
        uint4* ph = reinterpret_cast<uint4*>(sH);
        for (int i = tid; i < (64 * GASTR) / 8; i += 256) pa[i] = z;
        for (int i = tid; i < (64 * GHSTR) / 8; i += 256) ph[i] = z;
    }
    __syncthreads();

    const uint32_t a_base = smem_u32(sA);
    const uint32_t h_base = smem_u32(sH);
    const uint32_t a_off = (uint32_t)((warp_m * 32 + (lane & 15)) * GASTR + (lane >> 4) * 8);

    for (int pass = 0; pass < 2; ++pass) {
        for (int i = tid; i < 1250; i += 256) {
            int r = i / 25, c2 = i % 25;
            float2 av = *reinterpret_cast<const float2*>(
                Aadj + (size_t)b * 5000 + r * 100 + pass * 50 + c2 * 2);
            *reinterpret_cast<unsigned*>(sA + r * GASTR + c2 * 2) = pkh2(av.x, av.y);
        }
        for (int i = tid; i < 800; i += 256) {
            int j = i >> 4, v = i & 15;
            *reinterpret_cast<uint4*>(sH + j * GHSTR + v * 8) =
                *reinterpret_cast<const uint4*>(
                    g_bigH + ((size_t)(b * 50 + j)) * 640 + pass * 128 + v * 8);
        }
        __syncthreads();

        float acc[2][4][4];
#pragma unroll
        for (int i = 0; i < 2; ++i)
#pragma unroll
            for (int j = 0; j < 4; ++j)
#pragma unroll
                for (int r = 0; r < 4; ++r) acc[i][j][r] = 0.0f;

#pragma unroll
        for (int ks = 0; ks < 4; ++ks) {
            uint32_t a[2][4], bf[4][2];
#pragma unroll
            for (int mt = 0; mt < 2; ++mt)
                LDSM_X4(a[mt][0], a[mt][1], a[mt][2], a[mt][3],
                        a_base + (a_off + mt * 16 * GASTR + ks * 16) * 2);
#pragma unroll
            for (int nt = 0; nt < 4; ++nt) {
                uint32_t addr = h_base +
                    (uint32_t)(((ks * 16 + (lane & 15)) * GHSTR) +
                               warp_n * 32 + nt * 8) * 2;
                LDSM_X2_TRANS(bf[nt][0], bf[nt][1], addr);
            }
#pragma unroll
            for (int mt = 0; mt < 2; ++mt)
#pragma unroll
                for (int nt = 0; nt < 4; ++nt)
                    MMA_F16(acc[mt][nt][0], acc[mt][nt][1], acc[mt][nt][2], acc[mt][nt][3],
                            a[mt][0], a[mt][1], a[mt][2], a[mt][3],
                            bf[nt][0], bf[nt][1]);
        }

        const int er = warp_m * 32 + (lane >> 2);
        const int ec = warp_n * 32 + (lane & 3) * 2;
        const float* bb = pass ? b_oah : b_iah;
#pragma unroll
        for (int mt = 0; mt < 2; ++mt)
#pragma unroll
            for (int nt = 0; nt < 4; ++nt) {
                int i0 = er + mt * 16;
                int d = ec + nt * 8;
                float b0 = bb[d], b1 = bb[d + 1];
                if (i0 < 50)
                    *reinterpret_cast<unsigned*>(
                        g_inpH + ((size_t)b * 50 + i0) * 256 + pass * 128 + d) =
                        pkh2(acc[mt][nt][0] + b0, acc[mt][nt][1] + b1);
                if (i0 + 8 < 50)
                    *reinterpret_cast<unsigned*>(
                        g_inpH + ((size_t)b * 50 + i0 + 8) * 256 + pass * 128 + d) =
                        pkh2(acc[mt][nt][2] + b0, acc[mt][nt][3] + b1);
            }
        __syncthreads();
    }
}

// ---------------------------------------------------------------------------
// Fused GRU update + seq gather (one block per batch); half2 gate math
// ---------------------------------------------------------------------------
__global__ __launch_bounds__(256)
void gru_seq_kernel(const int* __restrict__ alias,
                    const int* __restrict__ lens,
                    float* __restrict__ out_seq) {
    __shared__ float sH[Nn * Dd];
    const int b = blockIdx.x, tid = threadIdx.x;

    for (int idx = tid; idx < Nn * 64; idx += 256) {
        int n = idx >> 6, d2 = idx & 63;
        size_t row = (size_t)b * Nn + n;
        const __half2* gi = reinterpret_cast<const __half2*>(g_giH + row * 384);
        const __half2* gh = reinterpret_cast<const __half2*>(g_bigH + row * 640 + 256);
        const __half2* hh = reinterpret_cast<const __half2*>(g_hiddenH + row * 128);
        float2 i_r = __half22float2(gi[d2]);
        float2 i_i = __half22float2(gi[64 + d2]);
        float2 i_n = __half22float2(gi[128 + d2]);
        float2 h_r = __half22float2(gh[d2]);
        float2 h_i = __half22float2(gh[64 + d2]);
        float2 h_n = __half22float2(gh[128 + d2]);
        float2 h   = __half22float2(hh[d2]);
        float rg0 = sigmoidf_(i_r.x + h_r.x), rg1 = sigmoidf_(i_r.y + h_r.y);
        float ig0 = sigmoidf_(i_i.x + h_i.x), ig1 = sigmoidf_(i_i.y + h_i.y);
        float ng0 = tanhf(i_n.x + rg0 * h_n.x), ng1 = tanhf(i_n.y + rg1 * h_n.y);
        float2 o = {ng0 + ig0 * (h.x - ng0), ng1 + ig1 * (h.y - ng1)};
        *reinterpret_cast<float2*>(sH + n * Dd + d2 * 2) = o;
    }
    __syncthreads();

    const int len1 = lens[b] - 1;
    for (int i = tid; i < Ll * 32; i += 256) {
        int l = i >> 5, c4 = i & 31;
        int a = alias[b * Ll + l];
        float4 v = reinterpret_cast<const float4*>(sH)[a * 32 + c4];
        size_t row = (size_t)b * Ll + l;
        reinterpret_cast<float4*>(out_seq)[row * 32 + c4] = v;
        uint2 hv;
        hv.x = pkh2(v.x, v.y);
        hv.y = pkh2(v.z, v.w);
        *reinterpret_cast<uint2*>(g_seqH + row * 128 + c4 * 4) = hv;
        if (l == len1)
            reinterpret_cast<float4*>(g_ht)[(size_t)b * 32 + c4] = v;
    }
}

// ---------------------------------------------------------------------------
// attention reduce (fp16 inputs, half2)
// ---------------------------------------------------------------------------
__global__ void attn_reduce_kernel() {
    int b = blockIdx.x * 2 + (threadIdx.x >> 6);
    int d2 = threadIdx.x & 63;
    const __half2* ap = reinterpret_cast<const __half2*>(g_alpH + (size_t)b * Ll * Dd) + d2;
    const __half2* sp = reinterpret_cast<const __half2*>(g_seqH + (size_t)b * Ll * Dd) + d2;
    float2 s = {0.0f, 0.0f};
#pragma unroll 10
    for (int l = 0; l < Ll; ++l) {
        float2 a = __half22float2(ap[l * 64]);
        float2 v = __half22float2(sp[l * 64]);
        s.x += a.x * v.x;
        s.y += a.y * v.y;
    }
    *reinterpret_cast<float2*>(g_aht + (size_t)b * 256 + d2 * 2) = s;
    *reinterpret_cast<float2*>(g_aht + (size_t)b * 256 + 128 + d2 * 2) =
        *reinterpret_cast<const float2*>(g_ht + (size_t)b * Dd + d2 * 2);
}

// ---------------------------------------------------------------------------
// Small fp32 SGEMM for q1 and final projection (M=1024 only)
// ---------------------------------------------------------------------------
__global__ __launch_bounds__(256)
void sgemm_kernel(const float* __restrict__ A, const float* __restrict__ W,
                  const float* __restrict__ bias, float* __restrict__ C,
                  int M, int Nout, int K) {
    __shared__ float As[16][128];
    __shared__ float Bs[16][128];
    const int tid = threadIdx.x;
    const int bm = blockIdx.y * 128, bn = blockIdx.x * 128;
    const int trow = (tid >> 4) << 3, tcol = (tid & 15) << 3;

    float acc[8][8];
#pragma unroll
    for (int i = 0; i < 8; ++i)
#pragma unroll
        for (int j = 0; j < 8; ++j) acc[i][j] = 0.0f;

    const float* Aptr = A + (size_t)bm * K;
    const float* Wptr = W + (size_t)bn * K;

    for (int k0 = 0; k0 < K; k0 += 16) {
#pragma unroll
        for (int it = 0; it < 2; ++it) {
            int idx = tid + it * 256;
            int r = idx >> 2, kk = (idx & 3) << 2;
            float4 va = *reinterpret_cast<const float4*>(Aptr + (size_t)r * K + k0 + kk);
            As[kk + 0][r] = va.x; As[kk + 1][r] = va.y;
            As[kk + 2][r] = va.z; As[kk + 3][r] = va.w;
            float4 vb = *reinterpret_cast<const float4*>(Wptr + (size_t)r * K + k0 + kk);
            Bs[kk + 0][r] = vb.x; Bs[kk + 1][r] = vb.y;
            Bs[kk + 2][r] = vb.z; Bs[kk + 3][r] = vb.w;
        }
        __syncthreads();
#pragma unroll
        for (int k = 0; k < 16; ++k) {
            float a[8], b[8];
            *reinterpret_cast<float4*>(&a[0]) = *reinterpret_cast<const float4*>(&As[k][trow]);
            *reinterpret_cast<float4*>(&a[4]) = *reinterpret_cast<const float4*>(&As[k][trow + 4]);
            *reinterpret_cast<float4*>(&b[0]) = *reinterpret_cast<const float4*>(&Bs[k][tcol]);
            *reinterpret_cast<float4*>(&b[4]) = *reinterpret_cast<const float4*>(&Bs[k][tcol + 4]);
#pragma unroll
            for (int i = 0; i < 8; ++i)
#pragma unroll
                for (int j = 0; j < 8; ++j)
                    acc[i][j] += a[i] * b[j];
        }
        __syncthreads();
    }
#pragma unroll
    for (int i = 0; i < 8; ++i) {
        int row = bm + trow + i;
#pragma unroll
        for (int j = 0; j < 8; j += 4) {
            int col = bn + tcol + j;
            float4 v;
            v.x = acc[i][j + 0] + bias[col + 0];
            v.y = acc[i][j + 1] + bias[col + 1];
            v.z = acc[i][j + 2] + bias[col + 2];
            v.w = acc[i][j + 3] + bias[col + 3];
            *reinterpret_cast<float4*>(C + (size_t)row * Nout + col) = v;
        }
    }
}

// ---------------------------------------------------------------------------
// Launch
// ---------------------------------------------------------------------------
extern "C" void kernel_launch(void* const* d_in, const int* in_sizes, int n_in,
                              void* d_out, int out_size) {
    const int*   items  = (const int*)  d_in[0];
    const float* Aadj   = (const float*)d_in[1];
    const int*   alias  = (const int*)  d_in[2];
    const int*   lens   = (const int*)  d_in[4];
    const float* emb    = (const float*)d_in[5];
    const float* w_ih   = (const float*)d_in[6];
    const float* w_hh   = (const float*)d_in[7];
    const float* b_ih   = (const float*)d_in[8];
    const float* b_hh   = (const float*)d_in[9];
    const float* b_iah  = (const float*)d_in[10];
    const float* b_oah  = (const float*)d_in[11];
    const float* w_in   = (const float*)d_in[12];
    const float* bi_in  = (const float*)d_in[13];
    const float* w_out  = (const float*)d_in[14];
    const float* bi_out = (const float*)d_in[15];
    const float* w1     = (const float*)d_in[16];
    const float* b1     = (const float*)d_in[17];
    const float* w2     = (const float*)d_in[18];
    const float* b2     = (const float*)d_in[19];
    const float* w3     = (const float*)d_in[20];
    const float* b3     = (const float*)d_in[21];
    const float* wt     = (const float*)d_in[22];
    const float* bt     = (const float*)d_in[23];

    float* out      = (float*)d_out;
    float* out_seq2 = out + (size_t)Bsz * Ll * Dd;

    void* p;
    cudaGetSymbolAddress(&p, g_hiddenH);  __half* hiddenH = (__half*)p;
    cudaGetSymbolAddress(&p, g_WcatH);    __half* WcatH   = (__half*)p;
    cudaGetSymbolAddress(&p, g_bcat);     float*  bcat    = (float*)p;
    cudaGetSymbolAddress(&p, g_bigH);     __half* bigH    = (__half*)p;
    cudaGetSymbolAddress(&p, g_inpH);     __half* inpH    = (__half*)p;
    cudaGetSymbolAddress(&p, g_wihH);     __half* wihH    = (__half*)p;
    cudaGetSymbolAddress(&p, g_giH);      __half* giH     = (__half*)p;
    cudaGetSymbolAddress(&p, g_seqH);     __half* seqH    = (__half*)p;
    cudaGetSymbolAddress(&p, g_w2H);      __half* w2H     = (__half*)p;
    cudaGetSymbolAddress(&p, g_w3H);      __half* w3H     = (__half*)p;
    cudaGetSymbolAddress(&p, g_alpH);     __half* alpH    = (__half*)p;
    cudaGetSymbolAddress(&p, g_ht);       float*  ht      = (float*)p;
    cudaGetSymbolAddress(&p, g_q1);       float*  q1      = (float*)p;
    cudaGetSymbolAddress(&p, g_aht);      float*  aht     = (float*)p;

    cudaFuncSetAttribute(hgemm_kernel, cudaFuncAttributeMaxDynamicSharedMemorySize,
                         HGEMM_SMEM3);

    // 1) merged prep: hiddenH gather + weight conversion
    prep_kernel<<<7232, 256>>>(items, emb, w_in, w_out, w_hh, bi_in, bi_out, b_hh,
                               w_ih, w2, w3);
    // 2) bigH = hidden @ [w_in|w_out|w_hh]^T + bias   (fp16 out)
    hgemm_kernel<<<dim3(5, Mrows / 64), 256, HGEMM_SMEM2>>>(
        hiddenH, WcatH, bcat, bigH, nullptr, nullptr, nullptr,
        128, 640, nullptr, 2);
    // 3) graph matmul (HMMA, trans-B) -> inpH
    graph_mm_kernel<<<Bsz, 256>>>(Aadj, b_iah, b_oah);
    // 4) giH = inp @ w_ih^T + b_ih   (fp16 out)
    hgemm_kernel<<<dim3(3, Mrows / 64), 256, HGEMM_SMEM2>>>(
        inpH, wihH, b_ih, giH, nullptr, nullptr, nullptr,
        256, 384, nullptr, 2);
    // 5) fused GRU update + seq gather (-> d_out, seqH, ht)
    gru_seq_kernel<<<Bsz, 256>>>(alias, lens, out);
    // 6) q1 = ht @ w1^T + b1  (fp32, small)
    sgemm_kernel<<<dim3(1, Bsz / 128), 256>>>(ht, w1, b1, q1, Bsz, 128, 128);
    // 7) fused: alpH = fp16[ sigmoid(seq@w2^T + b2 + q1) @ w3^T + b3 ]
    hgemm_kernel<<<dim3(1, Mrows / 64), 256, HGEMM_SMEM3>>>(
        seqH, w2H, b2, nullptr, w3H, b3, alpH,
        128, 128, q1, 3);
    // 8) attention reduce (fp16 in)
    attn_reduce_kernel<<<Bsz / 2, 128>>>();
    // 9) seq_output = [a|ht] @ wt^T + bt  (fp32, small)
    sgemm_kernel<<<dim3(1, Bsz / 128), 256>>>(aht, wt, bt, out_seq2, Bsz, 128, 256);
}

// round 16
// speedup vs baseline: 1.0575x; 1.0575x over previous
#include <cuda_runtime.h>
#include <cuda_fp16.h>
#include <cstdint>

// Problem constants
#define Bsz 1024
#define Nn  50
#define Ll  50
#define Dd  128
#define Mrows (Bsz * Nn)   // 51200

// ---------------------------------------------------------------------------
// Device scratch. Pure fp16 operands.
// ---------------------------------------------------------------------------
__device__ __align__(256) __half  g_hiddenH[Mrows * 128];
__device__ __align__(256) __half  g_bigH[Mrows * 640];      // [h_in|h_out|gh(384)]
__device__ __align__(256) __half  g_inpH[Mrows * 256];      // [in|out]
__device__ __align__(256) __half  g_giH[Mrows * 384];
__device__ __align__(256) __half  g_seqH[Mrows * 128];
__device__ __align__(256) __half  g_alpH[Mrows * 128];
__device__ __align__(256) float   g_ht[Bsz * Dd];
__device__ __align__(256) float   g_q1[Bsz * Dd];
__device__ __align__(256) float   g_aht[Bsz * 256];
__device__ __align__(256) __half  g_WcatH[640 * 128];
__device__ __align__(256) __half  g_wihH[384 * 256];
__device__ __align__(256) __half  g_w2H[128 * 128];
__device__ __align__(256) __half  g_w3H[128 * 128];
__device__ __align__(256) float   g_bcat[640];

__device__ __forceinline__ float sigmoidf_(float x) {
    return 1.0f / (1.0f + __expf(-x));
}
__device__ __forceinline__ unsigned pkh2(float a, float b) {
    __half ha = __float2half_rn(a), hb = __float2half_rn(b);
    unsigned short ua = *reinterpret_cast<unsigned short*>(&ha);
    unsigned short ub = *reinterpret_cast<unsigned short*>(&hb);
    return (unsigned)ua | ((unsigned)ub << 16);
}
__device__ __forceinline__ uint32_t smem_u32(const void* p) {
    uint32_t a;
    asm("{ .reg .u64 t; cvta.to.shared.u64 t, %1; cvt.u32.u64 %0, t; }" : "=r"(a) : "l"(p));
    return a;
}

// ---------------------------------------------------------------------------
// Portable tensor-core primitives (compute_103-safe PTX)
// ---------------------------------------------------------------------------
#define CP_ASYNC16(sm, gm) \
    asm volatile("cp.async.cg.shared.global [%0], [%1], 16;" :: "r"(sm), "l"(gm))
#define CP_COMMIT() asm volatile("cp.async.commit_group;" ::: "memory")
#define CP_WAIT0()  asm volatile("cp.async.wait_group 0;" ::: "memory")

#define LDSM_X4(r0, r1, r2, r3, addr) \
    asm volatile("ldmatrix.sync.aligned.m8n8.x4.shared.b16 {%0,%1,%2,%3}, [%4];" \
                 : "=r"(r0), "=r"(r1), "=r"(r2), "=r"(r3) : "r"(addr))
#define LDSM_X2(r0, r1, addr) \
    asm volatile("ldmatrix.sync.aligned.m8n8.x2.shared.b16 {%0,%1}, [%2];" \
                 : "=r"(r0), "=r"(r1) : "r"(addr))
#define LDSM_X2_TRANS(r0, r1, addr) \
    asm volatile("ldmatrix.sync.aligned.m8n8.x2.trans.shared.b16 {%0,%1}, [%2];" \
                 : "=r"(r0), "=r"(r1) : "r"(addr))

#define MMA_F16(c0, c1, c2, c3, a0, a1, a2, a3, b0, b1) \
    asm volatile("mma.sync.aligned.m16n8k16.row.col.f32.f16.f16.f32 " \
                 "{%0,%1,%2,%3}, {%4,%5,%6,%7}, {%8,%9}, {%0,%1,%2,%3};" \
                 : "+f"(c0), "+f"(c1), "+f"(c2), "+f"(c3) \
                 : "r"(a0), "r"(a1), "r"(a2), "r"(a3), "r"(b0), "r"(b1))

// ---------------------------------------------------------------------------
// Merged prep: blocks [0,6400) gather hiddenH; blocks [6400,7232) convert W.
// ---------------------------------------------------------------------------
__global__ void prep_kernel(const int* __restrict__ items,
                            const float* __restrict__ emb,
                            const float* __restrict__ w_in,
                            const float* __restrict__ w_out,
                            const float* __restrict__ w_hh,
                            const float* __restrict__ bi_in,
                            const float* __restrict__ bi_out,
                            const float* __restrict__ b_hh,
                            const float* __restrict__ w_ih,
                            const float* __restrict__ w2,
                            const float* __restrict__ w3) {
    if (blockIdx.x < 6400) {
        int idx = blockIdx.x * 256 + threadIdx.x;   // Mrows * 32
        int row = idx >> 5, c4 = idx & 31;
        int it = items[row];
        float4 v = reinterpret_cast<const float4*>(emb)[(size_t)it * 32 + c4];
        uint2 hv;
        hv.x = pkh2(v.x, v.y);
        hv.y = pkh2(v.z, v.w);
        *reinterpret_cast<uint2*>(g_hiddenH + (size_t)row * 128 + c4 * 4) = hv;
        return;
    }
    int i = (blockIdx.x - 6400) * 256 + threadIdx.x;
    const int S0 = 640 * 128, S1 = 384 * 256, S2 = 128 * 128;
    if (i < S0) {
        int r = i >> 7, c = i & 127;
        float v = (r < 128) ? w_in[r * 128 + c]
                : (r < 256) ? w_out[(r - 128) * 128 + c]
                            : w_hh[(r - 256) * 128 + c];
        g_WcatH[i] = __float2half_rn(v);
    } else if (i < S0 + S1) {
        g_wihH[i - S0] = __float2half_rn(w_ih[i - S0]);
    } else if (i < S0 + S1 + S2) {
        g_w2H[i - S0 - S1] = __float2half_rn(w2[i - S0 - S1]);
    } else if (i < S0 + S1 + 2 * S2) {
        g_w3H[i - S0 - S1 - S2] = __float2half_rn(w3[i - S0 - S1 - S2]);
    }
    if (i < 640)
        g_bcat[i] = (i < 128) ? bi_in[i] : (i < 256 ? bi_out[i - 128] : b_hh[i - 256]);
}

// ---------------------------------------------------------------------------
// HMMA fp16 GEMM (R14 winner): C(128x128 tile) = A(MxK) @ W(NoutxK)^T + bias
// Group-resident loading: 4 chunks (K=128) issued up-front, ONE barrier,
// then 128 MMAs with zero barriers. K=256 runs as 2 groups.
// smem: 8 stages x 10240 = 81920 (A in stages 0-3, W in stages 4-7).
// mode 2: fp16 out Ch at stride ldc
// mode 3: fused attention double-GEMM (gridDim.x == 1, Kbase == 128)
// ---------------------------------------------------------------------------
#define SMSTR 40
#define STG_BYTES (128 * SMSTR * 2)    // 10240
#define HGEMM_SMEM (8 * STG_BYTES)     // 81920

__global__ __launch_bounds__(256, 2)
void hgemm_kernel(const __half* __restrict__ A2,
                  const __half* __restrict__ W2,
                  const float* __restrict__ bias,
                  __half* __restrict__ Ch,
                  const __half* __restrict__ W3, const float* __restrict__ bias3,
                  __half* __restrict__ CalpH,
                  int Kbase, int ldc, const float* __restrict__ aux, int mode) {
    extern __shared__ __align__(16) __half smem[];

    const int tid = threadIdx.x;
    const int lane = tid & 31;
    const int wid = tid >> 5;
    const int warp_m = wid >> 2;
    const int warp_n = wid & 3;
    const int bm = blockIdx.y * 128, bn = blockIdx.x * 128;
    const int ngrp = Kbase >> 7;

    const int l_row0 = tid >> 1;
    const int l_seg0 = (tid & 1) << 1;
    const uint32_t sbase = smem_u32(smem);
    const uint32_t SBOFF = 4 * STG_BYTES;
    const uint32_t stA = (uint32_t)(l_row0 * SMSTR + l_seg0 * 8) * 2;
    const __half* Abase = A2 + (size_t)(bm + l_row0) * Kbase + l_seg0 * 8;
    const __half* Wbase = W2 + (size_t)(bn + l_row0) * Kbase + l_seg0 * 8;

#define ISSUE(cc, st) do {                                                     \
        uint32_t da = sbase + (uint32_t)(st) * STG_BYTES + stA;                \
        uint32_t db = sbase + SBOFF + (uint32_t)(st) * STG_BYTES + stA;        \
        const __half* ga = Abase + (cc) * 32;                                  \
        const __half* gb = Wbase + (cc) * 32;                                  \
        CP_ASYNC16(da,      ga);                                               \
        CP_ASYNC16(da + 16, ga + 8);                                           \
        CP_ASYNC16(db,      gb);                                               \
        CP_ASYNC16(db + 16, gb + 8);                                           \
    } while (0)

    float acc[4][4][4];
#pragma unroll
    for (int i = 0; i < 4; ++i)
#pragma unroll
        for (int j = 0; j < 4; ++j)
#pragma unroll
            for (int r = 0; r < 4; ++r) acc[i][j][r] = 0.0f;

    const uint32_t a_off = (uint32_t)((warp_m * 64 + (lane & 15)) * SMSTR + (lane >> 4) * 8);
    const uint32_t b_off = (uint32_t)((warp_n * 32 + (lane & 7)) * SMSTR + ((lane >> 3) & 1) * 8);

    for (int g = 0; g < ngrp; ++g) {
#pragma unroll
        for (int cc = 0; cc < 4; ++cc)
            ISSUE(g * 4 + cc, cc);
        CP_COMMIT();
        CP_WAIT0();
        __syncthreads();

#pragma unroll
        for (int cc = 0; cc < 4; ++cc) {
            const uint32_t baseA = sbase + cc * STG_BYTES;
            const uint32_t baseB = sbase + SBOFF + cc * STG_BYTES;
#pragma unroll
            for (int ks = 0; ks < 2; ++ks) {
                uint32_t a[4][4], b[4][2];
#pragma unroll
                for (int mt = 0; mt < 4; ++mt)
                    LDSM_X4(a[mt][0], a[mt][1], a[mt][2], a[mt][3],
                            baseA + (a_off + mt * 16 * SMSTR + ks * 16) * 2);
#pragma unroll
                for (int nt = 0; nt < 4; ++nt)
                    LDSM_X2(b[nt][0], b[nt][1],
                            baseB + (b_off + nt * 8 * SMSTR + ks * 16) * 2);
#pragma unroll
                for (int mt = 0; mt < 4; ++mt)
#pragma unroll
                    for (int nt = 0; nt < 4; ++nt)
                        MMA_F16(acc[mt][nt][0], acc[mt][nt][1], acc[mt][nt][2], acc[mt][nt][3],
                                a[mt][0], a[mt][1], a[mt][2], a[mt][3],
                                b[nt][0], b[nt][1]);
            }
        }
        if (g + 1 < ngrp) __syncthreads();
    }
#undef ISSUE

    const int er = warp_m * 64 + (lane >> 2);
    const int ec = warp_n * 32 + (lane & 3) * 2;

    if (mode == 2) {
#pragma unroll
        for (int mt = 0; mt < 4; ++mt)
#pragma unroll
            for (int nt = 0; nt < 4; ++nt) {
                int row = bm + er + mt * 16;
                int col = bn + ec + nt * 8;
                float b0 = bias[col], b1 = bias[col + 1];
                unsigned h0 = pkh2(acc[mt][nt][0] + b0, acc[mt][nt][1] + b1);
                unsigned h1 = pkh2(acc[mt][nt][2] + b0, acc[mt][nt][3] + b1);
                *reinterpret_cast<unsigned*>(Ch + (size_t)row * ldc + col) = h0;
                *reinterpret_cast<unsigned*>(Ch + (size_t)(row + 8) * ldc + col) = h1;
            }
    } else {
        // ---- mode 3: fused sigmoid -> smem (stages 0-3) -> GEMM2 with W3 ----
        __syncthreads();
        char* smc = reinterpret_cast<char*>(smem);
        const uint32_t W3OFF = SBOFF;
#pragma unroll
        for (int mt = 0; mt < 4; ++mt)
#pragma unroll
            for (int nt = 0; nt < 4; ++nt) {
                int col = ec + nt * 8;
                float b0 = bias[col], b1 = bias[col + 1];
                int chunk = col >> 5, kk = col & 31;
#pragma unroll
                for (int h = 0; h < 2; ++h) {
                    int rl = er + mt * 16 + h * 8;
                    const float* ap = aux + (size_t)((bm + rl) / 50) * 128;
                    float v0 = sigmoidf_(acc[mt][nt][h * 2 + 0] + b0 + ap[col]);
                    float v1 = sigmoidf_(acc[mt][nt][h * 2 + 1] + b1 + ap[col + 1]);
                    *reinterpret_cast<unsigned*>(
                        smc + chunk * STG_BYTES + rl * (SMSTR * 2) + kk * 2) =
                        pkh2(v0, v1);
                }
            }
        {
            int row = tid >> 1, seg = (tid & 1) << 1;
            const uint4* w3v = reinterpret_cast<const uint4*>(W3);
#pragma unroll
            for (int cch = 0; cch < 4; ++cch) {
                uint4 v0 = w3v[row * 16 + cch * 4 + seg];
                uint4 v1 = w3v[row * 16 + cch * 4 + seg + 1];
                char* dst = smc + W3OFF + cch * STG_BYTES + row * (SMSTR * 2) + seg * 16;
                *reinterpret_cast<uint4*>(dst)      = v0;
                *reinterpret_cast<uint4*>(dst + 16) = v1;
            }
        }
        __syncthreads();
        float acc2[4][4][4];
#pragma unroll
        for (int i = 0; i < 4; ++i)
#pragma unroll
            for (int j = 0; j < 4; ++j)
#pragma unroll
                for (int r = 0; r < 4; ++r) acc2[i][j][r] = 0.0f;
#pragma unroll
        for (int c2 = 0; c2 < 4; ++c2) {
            const uint32_t baseA = sbase + c2 * STG_BYTES;
            const uint32_t baseB = sbase + W3OFF + c2 * STG_BYTES;
#pragma unroll
            for (int ks = 0; ks < 2; ++ks) {
                uint32_t a[4][4], b[4][2];
#pragma unroll
                for (int mt = 0; mt < 4; ++mt)
                    LDSM_X4(a[mt][0], a[mt][1], a[mt][2], a[mt][3],
                            baseA + (a_off + mt * 16 * SMSTR + ks * 16) * 2);
#pragma unroll
                for (int nt = 0; nt < 4; ++nt)
                    LDSM_X2(b[nt][0], b[nt][1],
                            baseB + (b_off + nt * 8 * SMSTR + ks * 16) * 2);
#pragma unroll
                for (int mt = 0; mt < 4; ++mt)
#pragma unroll
                    for (int nt = 0; nt < 4; ++nt)
                        MMA_F16(acc2[mt][nt][0], acc2[mt][nt][1], acc2[mt][nt][2], acc2[mt][nt][3],
                                a[mt][0], a[mt][1], a[mt][2], a[mt][3],
                                b[nt][0], b[nt][1]);
            }
        }
#pragma unroll
        for (int mt = 0; mt < 4; ++mt)
#pragma unroll
            for (int nt = 0; nt < 4; ++nt) {
                int row = bm + er + mt * 16;
                int col = ec + nt * 8;
                float b0 = bias3[col], b1 = bias3[col + 1];
                unsigned h0 = pkh2(acc2[mt][nt][0] + b0, acc2[mt][nt][1] + b1);
                unsigned h1 = pkh2(acc2[mt][nt][2] + b0, acc2[mt][nt][3] + b1);
                *reinterpret_cast<unsigned*>(CalpH + (size_t)row * 128 + col) = h0;
                *reinterpret_cast<unsigned*>(CalpH + (size_t)(row + 8) * 128 + col) = h1;
            }
    }
}

// ---------------------------------------------------------------------------
// HMMA graph matmul with row-major h + ldmatrix.trans.
// ---------------------------------------------------------------------------
#define GASTR 72
#define GHSTR 136
__global__ __launch_bounds__(256)
void graph_mm_kernel(const float* __restrict__ Aadj,
                     const float* __restrict__ b_iah,
                     const float* __restrict__ b_oah) {
    __shared__ __align__(16) __half sA[64 * GASTR];
    __shared__ __align__(16) __half sH[64 * GHSTR];
    const int b = blockIdx.x, tid = threadIdx.x;
    const int lane = tid & 31, wid = tid >> 5;
    const int warp_m = wid >> 2;
    const int warp_n = wid & 3;

    {
        uint4 z = {0, 0, 0, 0};
        uint4* pa = reinterpret_cast<uint4*>(sA);
        uint4* ph = reinterpret_cast<uint4*>(sH);
        for (int i = tid; i < (64 * GASTR) / 8; i += 256) pa[i] = z;
        for (int i = tid; i < (64 * GHSTR) / 8; i += 256) ph[i] = z;
    }
    __syncthreads();

    const uint32_t a_base = smem_u32(sA);
    const uint32_t h_base = smem_u32(sH);
    const uint32_t a_off = (uint32_t)((warp_m * 32 + (lane & 15)) * GASTR + (lane >> 4) * 8);

    for (int pass = 0; pass < 2; ++pass) {
        for (int i = tid; i < 1250; i += 256) {
            int r = i / 25, c2 = i % 25;
            float2 av = *reinterpret_cast<const float2*>(
                Aadj + (size_t)b * 5000 + r * 100 + pass * 50 + c2 * 2);
            *reinterpret_cast<unsigned*>(sA + r * GASTR + c2 * 2) = pkh2(av.x, av.y);
        }
        for (int i = tid; i < 800; i += 256) {
            int j = i >> 4, v = i & 15;
            *reinterpret_cast<uint4*>(sH + j * GHSTR + v * 8) =
                *reinterpret_cast<const uint4*>(
                    g_bigH + ((size_t)(b * 50 + j)) * 640 + pass * 128 + v * 8);
        }
        __syncthreads();

        float acc[2][4][4];
#pragma unroll
        for (int i = 0; i < 2; ++i)
#pragma unroll
            for (int j = 0; j < 4; ++j)
#pragma unroll
                for (int r = 0; r < 4; ++r) acc[i][j][r] = 0.0f;

#pragma unroll
        for (int ks = 0; ks < 4; ++ks) {
            uint32_t a[2][4], bf[4][2];
#pragma unroll
            for (int mt = 0; mt < 2; ++mt)
                LDSM_X4(a[mt][0], a[mt][1], a[mt][2], a[mt][3],
                        a_base + (a_off + mt * 16 * GASTR + ks * 16) * 2);
#pragma unroll
            for (int nt = 0; nt < 4; ++nt) {
                uint32_t addr = h_base +
                    (uint32_t)(((ks * 16 + (lane & 15)) * GHSTR) +
                               warp_n * 32 + nt * 8) * 2;
                LDSM_X2_TRANS(bf[nt][0], bf[nt][1], addr);
            }
#pragma unroll
            for (int mt = 0; mt < 2; ++mt)
#pragma unroll
                for (int nt = 0; nt < 4; ++nt)
                    MMA_F16(acc[mt][nt][0], acc[mt][nt][1], acc[mt][nt][2], acc[mt][nt][3],
                            a[mt][0], a[mt][1], a[mt][2], a[mt][3],
                            bf[nt][0], bf[nt][1]);
        }

        const int er = warp_m * 32 + (lane >> 2);
        const int ec = warp_n * 32 + (lane & 3) * 2;
        const float* bb = pass ? b_oah : b_iah;
#pragma unroll
        for (int mt = 0; mt < 2; ++mt)
#pragma unroll
            for (int nt = 0; nt < 4; ++nt) {
                int i0 = er + mt * 16;
                int d = ec + nt * 8;
                float b0 = bb[d], b1 = bb[d + 1];
                if (i0 < 50)
                    *reinterpret_cast<unsigned*>(
                        g_inpH + ((size_t)b * 50 + i0) * 256 + pass * 128 + d) =
                        pkh2(acc[mt][nt][0] + b0, acc[mt][nt][1] + b1);
                if (i0 + 8 < 50)
                    *reinterpret_cast<unsigned*>(
                        g_inpH + ((size_t)b * 50 + i0 + 8) * 256 + pass * 128 + d) =
                        pkh2(acc[mt][nt][2] + b0, acc[mt][nt][3] + b1);
            }
        __syncthreads();
    }
}

// ---------------------------------------------------------------------------
// Fused GRU update + seq gather + q1 GEMV (one block per batch)
// q1[b,:] = ht_b @ w1^T + b1 computed in-block (ht row lives in smem)
// ---------------------------------------------------------------------------
__global__ __launch_bounds__(256)
void gru_seq_kernel(const int* __restrict__ alias,
                    const int* __restrict__ lens,
                    float* __restrict__ out_seq,
                    const float* __restrict__ w1,
                    const float* __restrict__ b1) {
    __shared__ float sH[Nn * Dd];
    const int b = blockIdx.x, tid = threadIdx.x;

    for (int idx = tid; idx < Nn * 64; idx += 256) {
        int n = idx >> 6, d2 = idx & 63;
        size_t row = (size_t)b * Nn + n;
        const __half2* gi = reinterpret_cast<const __half2*>(g_giH + row * 384);
        const __half2* gh = reinterpret_cast<const __half2*>(g_bigH + row * 640 + 256);
        const __half2* hh = reinterpret_cast<const __half2*>(g_hiddenH + row * 128);
        float2 i_r = __half22float2(gi[d2]);
        float2 i_i = __half22float2(gi[64 + d2]);
        float2 i_n = __half22float2(gi[128 + d2]);
        float2 h_r = __half22float2(gh[d2]);
        float2 h_i = __half22float2(gh[64 + d2]);
        float2 h_n = __half22float2(gh[128 + d2]);
        float2 h   = __half22float2(hh[d2]);
        float rg0 = sigmoidf_(i_r.x + h_r.x), rg1 = sigmoidf_(i_r.y + h_r.y);
        float ig0 = sigmoidf_(i_i.x + h_i.x), ig1 = sigmoidf_(i_i.y + h_i.y);
        float ng0 = tanhf(i_n.x + rg0 * h_n.x), ng1 = tanhf(i_n.y + rg1 * h_n.y);
        float2 o = {ng0 + ig0 * (h.x - ng0), ng1 + ig1 * (h.y - ng1)};
        *reinterpret_cast<float2*>(sH + n * Dd + d2 * 2) = o;
    }
    __syncthreads();

    const int len1 = lens[b] - 1;
    const int hrow = alias[b * Ll + len1];

    for (int i = tid; i < Ll * 32; i += 256) {
        int l = i >> 5, c4 = i & 31;
        int a = alias[b * Ll + l];
        float4 v = reinterpret_cast<const float4*>(sH)[a * 32 + c4];
        size_t row = (size_t)b * Ll + l;
        reinterpret_cast<float4*>(out_seq)[row * 32 + c4] = v;
        uint2 hv;
        hv.x = pkh2(v.x, v.y);
        hv.y = pkh2(v.z, v.w);
        *reinterpret_cast<uint2*>(g_seqH + row * 128 + c4 * 4) = hv;
        if (l == len1)
            reinterpret_cast<float4*>(g_ht)[(size_t)b * 32 + c4] = v;
    }

    // q1[b,d] = b1[d] + sum_k sH[hrow*128+k] * w1[d*128+k]   (threads 0..127)
    if (tid < 128) {
        const float* hp = sH + hrow * Dd;
        const float4* wr = reinterpret_cast<const float4*>(w1 + tid * 128);
        float s = 0.0f;
#pragma unroll
        for (int k4 = 0; k4 < 32; ++k4) {
            float4 w = wr[k4];
            const float4 hv = *reinterpret_cast<const float4*>(hp + k4 * 4);
            s += w.x * hv.x + w.y * hv.y + w.z * hv.z + w.w * hv.w;
        }
        g_q1[(size_t)b * Dd + tid] = s + b1[tid];
    }
}

// ---------------------------------------------------------------------------
// attention reduce (fp16 inputs, half2)
// ---------------------------------------------------------------------------
__global__ void attn_reduce_kernel() {
    int b = blockIdx.x * 2 + (threadIdx.x >> 6);
    int d2 = threadIdx.x & 63;
    const __half2* ap = reinterpret_cast<const __half2*>(g_alpH + (size_t)b * Ll * Dd) + d2;
    const __half2* sp = reinterpret_cast<const __half2*>(g_seqH + (size_t)b * Ll * Dd) + d2;
    float2 s = {0.0f, 0.0f};
#pragma unroll 10
    for (int l = 0; l < Ll; ++l) {
        float2 a = __half22float2(ap[l * 64]);
        float2 v = __half22float2(sp[l * 64]);
        s.x += a.x * v.x;
        s.y += a.y * v.y;
    }
    *reinterpret_cast<float2*>(g_aht + (size_t)b * 256 + d2 * 2) = s;
    *reinterpret_cast<float2*>(g_aht + (size_t)b * 256 + 128 + d2 * 2) =
        *reinterpret_cast<const float2*>(g_ht + (size_t)b * Dd + d2 * 2);
}

// ---------------------------------------------------------------------------
// Small fp32 SGEMM for final projection (M=1024)
// ---------------------------------------------------------------------------
__global__ __launch_bounds__(256)
void sgemm_kernel(const float* __restrict__ A, const float* __restrict__ W,
                  const float* __restrict__ bias, float* __restrict__ C,
                  int M, int Nout, int K) {
    __shared__ float As[16][128];
    __shared__ float Bs[16][128];
    const int tid = threadIdx.x;
    const int bm = blockIdx.y * 128, bn = blockIdx.x * 128;
    const int trow = (tid >> 4) << 3, tcol = (tid & 15) << 3;

    float acc[8][8];
#pragma unroll
    for (int i = 0; i < 8; ++i)
#pragma unroll
        for (int j = 0; j < 8; ++j) acc[i][j] = 0.0f;

    const float* Aptr = A + (size_t)bm * K;
    const float* Wptr = W + (size_t)bn * K;

    for (int k0 = 0; k0 < K; k0 += 16) {
#pragma unroll
        for (int it = 0; it < 2; ++it) {
            int idx = tid + it * 256;
            int r = idx >> 2, kk = (idx & 3) << 2;
            float4 va = *reinterpret_cast<const float4*>(Aptr + (size_t)r * K + k0 + kk);
            As[kk + 0][r] = va.x; As[kk + 1][r] = va.y;
            As[kk + 2][r] = va.z; As[kk + 3][r] = va.w;
            float4 vb = *reinterpret_cast<const float4*>(Wptr + (size_t)r * K + k0 + kk);
            Bs[kk + 0][r] = vb.x; Bs[kk + 1][r] = vb.y;
            Bs[kk + 2][r] = vb.z; Bs[kk + 3][r] = vb.w;
        }
        __syncthreads();
#pragma unroll
        for (int k = 0; k < 16; ++k) {
            float a[8], b[8];
            *reinterpret_cast<float4*>(&a[0]) = *reinterpret_cast<const float4*>(&As[k][trow]);
            *reinterpret_cast<float4*>(&a[4]) = *reinterpret_cast<const float4*>(&As[k][trow + 4]);
            *reinterpret_cast<float4*>(&b[0]) = *reinterpret_cast<const float4*>(&Bs[k][tcol]);
            *reinterpret_cast<float4*>(&b[4]) = *reinterpret_cast<const float4*>(&Bs[k][tcol + 4]);
#pragma unroll
            for (int i = 0; i < 8; ++i)
#pragma unroll
                for (int j = 0; j < 8; ++j)
                    acc[i][j] += a[i] * b[j];
        }
        __syncthreads();
    }
#pragma unroll
    for (int i = 0; i < 8; ++i) {
        int row = bm + trow + i;
#pragma unroll
        for (int j = 0; j < 8; j += 4) {
            int col = bn + tcol + j;
            float4 v;
            v.x = acc[i][j + 0] + bias[col + 0];
            v.y = acc[i][j + 1] + bias[col + 1];
            v.z = acc[i][j + 2] + bias[col + 2];
            v.w = acc[i][j + 3] + bias[col + 3];
            *reinterpret_cast<float4*>(C + (size_t)row * Nout + col) = v;
        }
    }
}

// ---------------------------------------------------------------------------
// Launch
// ---------------------------------------------------------------------------
extern "C" void kernel_launch(void* const* d_in, const int* in_sizes, int n_in,
                              void* d_out, int out_size) {
    const int*   items  = (const int*)  d_in[0];
    const float* Aadj   = (const float*)d_in[1];
    const int*   alias  = (const int*)  d_in[2];
    const int*   lens   = (const int*)  d_in[4];
    const float* emb    = (const float*)d_in[5];
    const float* w_ih   = (const float*)d_in[6];
    const float* w_hh   = (const float*)d_in[7];
    const float* b_ih   = (const float*)d_in[8];
    const float* b_hh   = (const float*)d_in[9];
    const float* b_iah  = (const float*)d_in[10];
    const float* b_oah  = (const float*)d_in[11];
    const float* w_in   = (const float*)d_in[12];
    const float* bi_in  = (const float*)d_in[13];
    const float* w_out  = (const float*)d_in[14];
    const float* bi_out = (const float*)d_in[15];
    const float* w1     = (const float*)d_in[16];
    const float* b1     = (const float*)d_in[17];
    const float* w2     = (const float*)d_in[18];
    const float* b2     = (const float*)d_in[19];
    const float* w3     = (const float*)d_in[20];
    const float* b3     = (const float*)d_in[21];
    const float* wt     = (const float*)d_in[22];
    const float* bt     = (const float*)d_in[23];

    float* out      = (float*)d_out;
    float* out_seq2 = out + (size_t)Bsz * Ll * Dd;

    void* p;
    cudaGetSymbolAddress(&p, g_hiddenH);  __half* hiddenH = (__half*)p;
    cudaGetSymbolAddress(&p, g_WcatH);    __half* WcatH   = (__half*)p;
    cudaGetSymbolAddress(&p, g_bcat);     float*  bcat    = (float*)p;
    cudaGetSymbolAddress(&p, g_bigH);     __half* bigH    = (__half*)p;
    cudaGetSymbolAddress(&p, g_inpH);     __half* inpH    = (__half*)p;
    cudaGetSymbolAddress(&p, g_wihH);     __half* wihH    = (__half*)p;
    cudaGetSymbolAddress(&p, g_giH);      __half* giH     = (__half*)p;
    cudaGetSymbolAddress(&p, g_seqH);     __half* seqH    = (__half*)p;
    cudaGetSymbolAddress(&p, g_w2H);      __half* w2H     = (__half*)p;
    cudaGetSymbolAddress(&p, g_w3H);      __half* w3H     = (__half*)p;
    cudaGetSymbolAddress(&p, g_alpH);     __half* alpH    = (__half*)p;
    cudaGetSymbolAddress(&p, g_ht);       float*  ht      = (float*)p;
    cudaGetSymbolAddress(&p, g_q1);       float*  q1      = (float*)p;
    cudaGetSymbolAddress(&p, g_aht);      float*  aht     = (float*)p;

    cudaFuncSetAttribute(hgemm_kernel, cudaFuncAttributeMaxDynamicSharedMemorySize,
                         HGEMM_SMEM);

    // 1) merged prep: hiddenH gather + weight conversion
    prep_kernel<<<7232, 256>>>(items, emb, w_in, w_out, w_hh, bi_in, bi_out, b_hh,
                               w_ih, w2, w3);
    // 2) bigH = hidden @ [w_in|w_out|w_hh]^T + bias   (fp16 out)
    hgemm_kernel<<<dim3(5, Mrows / 128), 256, HGEMM_SMEM>>>(
        hiddenH, WcatH, bcat, bigH, nullptr, nullptr, nullptr,
        128, 640, nullptr, 2);
    // 3) graph matmul (HMMA, trans-B) -> inpH
    graph_mm_kernel<<<Bsz, 256>>>(Aadj, b_iah, b_oah);
    // 4) giH = inp @ w_ih^T + b_ih   (fp16 out)
    hgemm_kernel<<<dim3(3, Mrows / 128), 256, HGEMM_SMEM>>>(
        inpH, wihH, b_ih, giH, nullptr, nullptr, nullptr,
        256, 384, nullptr, 2);
    // 5) fused GRU update + seq gather + q1 GEMV
    gru_seq_kernel<<<Bsz, 256>>>(alias, lens, out, w1, b1);
    // 6) fused: alpH = fp16[ sigmoid(seq@w2^T + b2 + q1) @ w3^T + b3 ]
    hgemm_kernel<<<dim3(1, Mrows / 128), 256, HGEMM_SMEM>>>(
        seqH, w2H, b2, nullptr, w3H, b3, alpH,
        128, 128, q1, 3);
    // 7) attention reduce (fp16 in)
    attn_reduce_kernel<<<Bsz / 2, 128>>>();
    // 8) seq_output = [a|ht] @ wt^T + bt  (fp32, small)
    sgemm_kernel<<<dim3(1, Bsz / 128), 256>>>(aht, wt, bt, out_seq2, Bsz, 128, 256);
}